// round 3
// baseline (speedup 1.0000x reference)
#include <cuda_runtime.h>
#include <math.h>

#define BATCH 128
#define FEAT  1024
#define CLS   500
#define HID   512

// Scratch (device globals: no allocations allowed)
__device__ float g_imgT[HID * BATCH];        // img_part transposed [h][b], b1 folded in
__device__ float g_attr[CLS * HID];          // attr_part [c][h]
__device__ float g_part[3 * BATCH * CLS];    // partial dots per h-split, [c*128+b]

// ---------- f32x2 helpers (FFMA2: 2 fp32 FMAs per issue slot) ----------
__device__ __forceinline__ unsigned long long pk2(float x, float y) {
    unsigned long long r;
    asm("mov.b64 %0, {%1, %2};" : "=l"(r) : "f"(x), "f"(y));
    return r;
}
__device__ __forceinline__ float2 unpk2(unsigned long long v) {
    float2 r;
    asm("mov.b64 {%0, %1}, %2;" : "=f"(r.x), "=f"(r.y) : "l"(v));
    return r;
}
__device__ __forceinline__ void ffma2(unsigned long long& d,
                                      unsigned long long a, unsigned long long b) {
    asm("fma.rn.f32x2 %0, %1, %2, %0;" : "+l"(d) : "l"(a), "l"(b));
}

// ---------------------------------------------------------------------
// Fused GEMM: virtual rows [0,128) -> img_part = img @ W1[:, :F]^T (+b1, transposed out)
//             virtual rows [128,628) -> attr_part = attr @ W1[:, F:]^T
// Tile: BM=32 x BN=64 x BK=32, 256 threads, 2x4 per-thread micro-tile (f32x2 pairs on n)
// ---------------------------------------------------------------------
#define BM 32
#define BN 64
#define BK 32

__global__ __launch_bounds__(256) void gemm_proj(
    const float* __restrict__ img, const float* __restrict__ attr,
    const float* __restrict__ W1, const float* __restrict__ b1)
{
    __shared__ float As[BK][BM + 4];   // [k][m]
    __shared__ float Bs[BK][BN + 4];   // [k][n]

    const int tid = threadIdx.x;
    const int tx = tid & 15;           // n micro index (4 each)
    const int ty = tid >> 4;           // m micro index (2 each)
    const int by = blockIdx.y;         // 0..19 (0..3 img, 4..19 attr)
    const int n0 = blockIdx.x * BN;

    const bool is_img = (by < 4);
    const float* A    = is_img ? img : attr;
    const int row0    = is_img ? by * BM : by * BM - BATCH;
    const int rowsM   = is_img ? BATCH : CLS;
    const int koff    = is_img ? 0 : FEAT;

    const int la_m = tid >> 3;          // 0..31
    const int la_k = (tid & 7) * 4;     // 0,4,..,28
    const int lb_n = tid >> 3;
    const int lb_k = (tid & 7) * 4;

    unsigned long long acc00 = 0ull, acc01 = 0ull, acc10 = 0ull, acc11 = 0ull;

    for (int k0 = 0; k0 < FEAT; k0 += BK) {
        // Load A tile (32m x 32k), transposed into smem
        {
            const int r = row0 + la_m;
            float4 v = make_float4(0.f, 0.f, 0.f, 0.f);
            if (r < rowsM) v = *(const float4*)&A[(size_t)r * FEAT + k0 + la_k];
            As[la_k + 0][la_m] = v.x;
            As[la_k + 1][la_m] = v.y;
            As[la_k + 2][la_m] = v.z;
            As[la_k + 3][la_m] = v.w;
        }
        // Load B tile (64n x 32k): W1 rows are h, row stride 2*FEAT
        #pragma unroll
        for (int j = 0; j < 2; j++) {
            const int n = lb_n + j * 32;
            float4 v = *(const float4*)&W1[(size_t)(n0 + n) * (2 * FEAT) + koff + k0 + lb_k];
            Bs[lb_k + 0][n] = v.x;
            Bs[lb_k + 1][n] = v.y;
            Bs[lb_k + 2][n] = v.z;
            Bs[lb_k + 3][n] = v.w;
        }
        __syncthreads();

        #pragma unroll
        for (int kk = 0; kk < BK; kk++) {
            float2 a = *(float2*)&As[kk][ty * 2];
            ulonglong2 bb = *(ulonglong2*)&Bs[kk][tx * 4];   // (n0,n1),(n2,n3)
            unsigned long long a0 = pk2(a.x, a.x);
            unsigned long long a1 = pk2(a.y, a.y);
            ffma2(acc00, a0, bb.x);
            ffma2(acc01, a0, bb.y);
            ffma2(acc10, a1, bb.x);
            ffma2(acc11, a1, bb.y);
        }
        __syncthreads();
    }

    const int h = n0 + tx * 4;
    if (is_img) {
        const int b = by * BM + ty * 2;
        float2 c00 = unpk2(acc00), c01 = unpk2(acc01);
        float2 c10 = unpk2(acc10), c11 = unpk2(acc11);
        const float bb0 = b1[h + 0], bb1 = b1[h + 1];
        const float bb2 = b1[h + 2], bb3 = b1[h + 3];
        g_imgT[(h + 0) * BATCH + b]     = c00.x + bb0;
        g_imgT[(h + 1) * BATCH + b]     = c00.y + bb1;
        g_imgT[(h + 2) * BATCH + b]     = c01.x + bb2;
        g_imgT[(h + 3) * BATCH + b]     = c01.y + bb3;
        g_imgT[(h + 0) * BATCH + b + 1] = c10.x + bb0;
        g_imgT[(h + 1) * BATCH + b + 1] = c10.y + bb1;
        g_imgT[(h + 2) * BATCH + b + 1] = c11.x + bb2;
        g_imgT[(h + 3) * BATCH + b + 1] = c11.y + bb3;
    } else {
        const int c = row0 + ty * 2;
        if (c < CLS) {
            ulonglong2 v; v.x = acc00; v.y = acc01;
            *(ulonglong2*)&g_attr[(size_t)c * HID + h] = v;
        }
        if (c + 1 < CLS) {
            ulonglong2 v; v.x = acc10; v.y = acc11;
            *(ulonglong2*)&g_attr[(size_t)(c + 1) * HID + h] = v;
        }
    }
}

// ---------------------------------------------------------------------
// Broadcast relu-dot: part[c,b] += sum_h relu(imgT[h,b] + attr[c,h]) * W2[h]
// Grid: (ceil(500/8) c-tiles, 3 h-splits). 128 threads = one per b.
// ---------------------------------------------------------------------
#define CT  8
#define HCH 171

__global__ __launch_bounds__(128) void relscore(const float* __restrict__ W2)
{
    __shared__ float attr8[HCH][CT];
    __shared__ float w2s[HCH];

    const int b    = threadIdx.x;
    const int c0   = blockIdx.x * CT;
    const int h0   = blockIdx.y * HCH;
    const int hcnt = min(HCH, HID - h0);

    #pragma unroll
    for (int cc = 0; cc < CT; cc++) {
        const int c = c0 + cc;
        for (int hh = b; hh < hcnt; hh += 128)
            attr8[hh][cc] = (c < CLS) ? g_attr[(size_t)c * HID + h0 + hh] : 0.f;
    }
    for (int hh = b; hh < hcnt; hh += 128) w2s[hh] = W2[h0 + hh];
    __syncthreads();

    float acc[CT];
    #pragma unroll
    for (int i = 0; i < CT; i++) acc[i] = 0.f;

    const float* ip = g_imgT + (size_t)h0 * BATCH + b;

    #pragma unroll 4
    for (int hh = 0; hh < hcnt; hh++) {
        const float iv = ip[(size_t)hh * BATCH];   // coalesced across threads
        const float w  = w2s[hh];
        float4 a0 = *(float4*)&attr8[hh][0];
        float4 a1 = *(float4*)&attr8[hh][4];
        acc[0] += fmaxf(iv + a0.x, 0.f) * w;
        acc[1] += fmaxf(iv + a0.y, 0.f) * w;
        acc[2] += fmaxf(iv + a0.z, 0.f) * w;
        acc[3] += fmaxf(iv + a0.w, 0.f) * w;
        acc[4] += fmaxf(iv + a1.x, 0.f) * w;
        acc[5] += fmaxf(iv + a1.y, 0.f) * w;
        acc[6] += fmaxf(iv + a1.z, 0.f) * w;
        acc[7] += fmaxf(iv + a1.w, 0.f) * w;
    }

    float* part = g_part + (size_t)blockIdx.y * (BATCH * CLS);
    #pragma unroll
    for (int cc = 0; cc < CT; cc++) {
        const int c = c0 + cc;
        if (c < CLS) part[c * BATCH + b] = acc[cc];   // coalesced over b
    }
}

// ---------------------------------------------------------------------
// Finalize: out[b,c] = sigmoid(sum of 3 partials + b2)
// ---------------------------------------------------------------------
__global__ __launch_bounds__(256) void finalize(float* __restrict__ out,
                                                const float* __restrict__ b2)
{
    const int i = blockIdx.x * 256 + threadIdx.x;   // i = c*128 + b
    if (i >= BATCH * CLS) return;
    const int c = i >> 7;
    const int b = i & 127;
    float s = g_part[i] + g_part[BATCH * CLS + i] + g_part[2 * BATCH * CLS + i] + b2[0];
    out[b * CLS + c] = 1.f / (1.f + expf(-s));
}

// ---------------------------------------------------------------------
extern "C" void kernel_launch(void* const* d_in, const int* in_sizes, int n_in,
                              void* d_out, int out_size)
{
    const float* img  = (const float*)d_in[0];
    const float* attr = (const float*)d_in[1];
    const float* W1   = (const float*)d_in[2];
    const float* b1   = (const float*)d_in[3];
    const float* W2   = (const float*)d_in[4];
    const float* b2   = (const float*)d_in[5];
    float* out = (float*)d_out;

    gemm_proj<<<dim3(HID / BN, (BATCH + CLS + BM + BM - 1) / BM /* =20 */), 256>>>(img, attr, W1, b1);
    relscore<<<dim3((CLS + CT - 1) / CT /* 63 */, 3), 128>>>(W2);
    finalize<<<(BATCH * CLS + 255) / 256 /* 250 */, 256>>>(out, b2);
}

// round 6
// speedup vs baseline: 1.1565x; 1.1565x over previous
#include <cuda_runtime.h>
#include <math.h>

#define BATCH 128
#define FEAT  1024
#define CLS   500
#define HID   512

#define NSPLIT 4
#define KSP    (FEAT / NSPLIT)   // 256 k per split
#define HSPLIT 8
#define HCH    (HID / HSPLIT)    // 64

// Scratch (device globals: allocations forbidden)
__device__ float g_pimg[NSPLIT][HID * BATCH];    // img partials, [h][b] layout
__device__ float g_pattr[NSPLIT][512 * HID];     // attr partials, [c][h], c padded to 512
__device__ float g_imgT[HID * BATCH];            // reduced, b1 folded
__device__ float g_attr[512 * HID];              // reduced
__device__ float g_part[HSPLIT][CLS * BATCH];    // relscore partial dots [c*128+b]

// ---------- f32x2 helpers ----------
__device__ __forceinline__ unsigned long long pk2(float x, float y) {
    unsigned long long r;
    asm("mov.b64 %0, {%1, %2};" : "=l"(r) : "f"(x), "f"(y));
    return r;
}
__device__ __forceinline__ float2 unpk2(unsigned long long v) {
    float2 r;
    asm("mov.b64 {%0, %1}, %2;" : "=f"(r.x), "=f"(r.y) : "l"(v));
    return r;
}
__device__ __forceinline__ void ffma2(unsigned long long& d,
                                      unsigned long long a, unsigned long long b) {
    asm("fma.rn.f32x2 %0, %1, %2, %0;" : "+l"(d) : "l"(a), "l"(b));
}

// ---------------------------------------------------------------------
// Fused projection GEMM, K-split x4.
// Virtual m rows: [0,128) img -> partial [h][b]; [128,628+) attr -> partial [c][h].
// 64 threads, BM=32 x BN=64 x BK=32, micro-tile 4m x 8n (4 f32x2 pairs).
// Smem rows padded by +4 floats: row strides 144B/272B keep all 128-bit
// LDS accesses 16B-aligned (the +1 padding in R4 trapped on misalignment).
// ---------------------------------------------------------------------
#define BM 32
#define BN 64
#define BK 32

__global__ __launch_bounds__(64) void gemm_proj(
    const float* __restrict__ img, const float* __restrict__ attr,
    const float* __restrict__ W1)
{
    __shared__ float As[BK][BM + 4];   // [k][m]
    __shared__ float Bs[BK][BN + 4];   // [k][n]

    const int tid = threadIdx.x;
    const int tx  = tid & 7;           // n group (8 n each)
    const int ty  = tid >> 3;          // m group (4 m each)
    const int bx  = blockIdx.x;        // n tile (8)
    const int by  = blockIdx.y;        // m tile (20): 0..3 img, 4..19 attr
    const int bz  = blockIdx.z;        // k split (4)

    const bool is_img  = (by < 4);
    const float* A     = is_img ? img : attr;
    const int row0     = is_img ? by * BM : (by - 4) * BM;
    const int rowsM    = is_img ? BATCH : CLS;
    const int kbase    = bz * KSP;                       // feature offset for A
    const int kW       = (is_img ? 0 : FEAT) + kbase;    // column offset in W1
    const int n0       = bx * BN;

    unsigned long long acc[4][4];
    #pragma unroll
    for (int i = 0; i < 4; i++)
        #pragma unroll
        for (int j = 0; j < 4; j++) acc[i][j] = 0ull;

    for (int k0 = 0; k0 < KSP; k0 += BK) {
        // A tile: 32m x 32k = 256 float4 loads, 4 per thread
        #pragma unroll
        for (int i = 0; i < 4; i++) {
            const int idx = i * 64 + tid;
            const int m = idx >> 3, kq = idx & 7;
            const int r = row0 + m;
            float4 v = make_float4(0.f, 0.f, 0.f, 0.f);
            if (r < rowsM)
                v = *(const float4*)&A[(size_t)r * FEAT + kbase + k0 + kq * 4];
            As[kq * 4 + 0][m] = v.x;
            As[kq * 4 + 1][m] = v.y;
            As[kq * 4 + 2][m] = v.z;
            As[kq * 4 + 3][m] = v.w;
        }
        // B tile: 64n x 32k = 512 float4 loads, 8 per thread (W1 rows = h, stride 2F)
        #pragma unroll
        for (int i = 0; i < 8; i++) {
            const int idx = i * 64 + tid;
            const int n = idx >> 3, kq = idx & 7;
            float4 v = *(const float4*)&W1[(size_t)(n0 + n) * (2 * FEAT) + kW + k0 + kq * 4];
            Bs[kq * 4 + 0][n] = v.x;
            Bs[kq * 4 + 1][n] = v.y;
            Bs[kq * 4 + 2][n] = v.z;
            Bs[kq * 4 + 3][n] = v.w;
        }
        __syncthreads();

        #pragma unroll
        for (int kk = 0; kk < BK; kk++) {
            float4 a4 = *(float4*)&As[kk][ty * 4];
            unsigned long long a0 = pk2(a4.x, a4.x);
            unsigned long long a1 = pk2(a4.y, a4.y);
            unsigned long long a2 = pk2(a4.z, a4.z);
            unsigned long long a3 = pk2(a4.w, a4.w);
            ulonglong2 bL = *(ulonglong2*)&Bs[kk][tx * 8];
            ulonglong2 bH = *(ulonglong2*)&Bs[kk][tx * 8 + 4];
            ffma2(acc[0][0], a0, bL.x); ffma2(acc[0][1], a0, bL.y);
            ffma2(acc[0][2], a0, bH.x); ffma2(acc[0][3], a0, bH.y);
            ffma2(acc[1][0], a1, bL.x); ffma2(acc[1][1], a1, bL.y);
            ffma2(acc[1][2], a1, bH.x); ffma2(acc[1][3], a1, bH.y);
            ffma2(acc[2][0], a2, bL.x); ffma2(acc[2][1], a2, bL.y);
            ffma2(acc[2][2], a2, bH.x); ffma2(acc[2][3], a2, bH.y);
            ffma2(acc[3][0], a3, bL.x); ffma2(acc[3][1], a3, bL.y);
            ffma2(acc[3][2], a3, bH.x); ffma2(acc[3][3], a3, bH.y);
        }
        __syncthreads();
    }

    const int h = n0 + tx * 8;
    if (is_img) {
        // scatter to [h][b] partial (so reduce + relscore read coalesced)
        const int b0 = row0 + ty * 4;
        float* P = g_pimg[bz];
        #pragma unroll
        for (int i = 0; i < 4; i++)
            #pragma unroll
            for (int jj = 0; jj < 4; jj++) {
                float2 v = unpk2(acc[i][jj]);
                P[(h + 2 * jj)     * BATCH + b0 + i] = v.x;
                P[(h + 2 * jj + 1) * BATCH + b0 + i] = v.y;
            }
    } else {
        const int c = row0 + ty * 4;          // c rows padded to 512 -> no guard
        float* P = g_pattr[bz];
        #pragma unroll
        for (int i = 0; i < 4; i++) {
            ulonglong2 v0; v0.x = acc[i][0]; v0.y = acc[i][1];
            ulonglong2 v1; v1.x = acc[i][2]; v1.y = acc[i][3];
            *(ulonglong2*)&P[(size_t)(c + i) * HID + h]     = v0;
            *(ulonglong2*)&P[(size_t)(c + i) * HID + h + 4] = v1;
        }
    }
}

// ---------------------------------------------------------------------
// Fold 4 K-split partials; add b1 into imgT.
// ---------------------------------------------------------------------
__global__ __launch_bounds__(256) void reduce_parts(const float* __restrict__ b1)
{
    const int i = blockIdx.x * 256 + threadIdx.x;
    if (i < HID * BATCH) {
        const int h = i >> 7;
        g_imgT[i] = g_pimg[0][i] + g_pimg[1][i] + g_pimg[2][i] + g_pimg[3][i] + b1[h];
    } else {
        const int j = i - HID * BATCH;
        if (j < CLS * HID)
            g_attr[j] = g_pattr[0][j] + g_pattr[1][j] + g_pattr[2][j] + g_pattr[3][j];
    }
}

// ---------------------------------------------------------------------
// part[hs][c,b] = sum_{h in chunk} relu(imgT[h,b] + attr[c,h]) * W2[h]
// Grid: (63 c-tiles of 8, 8 h-splits of 64). 128 threads = one per b.
// ---------------------------------------------------------------------
#define CT 8

__global__ __launch_bounds__(128) void relscore(const float* __restrict__ W2)
{
    __shared__ float attr8[HCH][CT];
    __shared__ float w2s[HCH];

    const int b  = threadIdx.x;
    const int c0 = blockIdx.x * CT;
    const int h0 = blockIdx.y * HCH;

    // coalesced attr load: consecutive threads -> consecutive h
    for (int t = b; t < HCH * CT; t += 128) {
        const int cc = t / HCH, hh = t % HCH;
        const int c = c0 + cc;
        attr8[hh][cc] = (c < CLS) ? g_attr[(size_t)c * HID + h0 + hh] : 0.f;
    }
    if (b < HCH) w2s[b] = W2[h0 + b];
    __syncthreads();

    float acc[CT];
    #pragma unroll
    for (int i = 0; i < CT; i++) acc[i] = 0.f;

    const float* ip = g_imgT + (size_t)h0 * BATCH + b;

    #pragma unroll 8
    for (int hh = 0; hh < HCH; hh++) {
        const float iv = ip[(size_t)hh * BATCH];   // coalesced over threads
        const float w  = w2s[hh];
        float4 a0 = *(float4*)&attr8[hh][0];
        float4 a1 = *(float4*)&attr8[hh][4];
        acc[0] += fmaxf(iv + a0.x, 0.f) * w;
        acc[1] += fmaxf(iv + a0.y, 0.f) * w;
        acc[2] += fmaxf(iv + a0.z, 0.f) * w;
        acc[3] += fmaxf(iv + a0.w, 0.f) * w;
        acc[4] += fmaxf(iv + a1.x, 0.f) * w;
        acc[5] += fmaxf(iv + a1.y, 0.f) * w;
        acc[6] += fmaxf(iv + a1.z, 0.f) * w;
        acc[7] += fmaxf(iv + a1.w, 0.f) * w;
    }

    float* part = g_part[blockIdx.y];
    #pragma unroll
    for (int cc = 0; cc < CT; cc++) {
        const int c = c0 + cc;
        if (c < CLS) part[c * BATCH + b] = acc[cc];
    }
}

// ---------------------------------------------------------------------
// out[b,c] = sigmoid(sum of 8 partials + b2)
// ---------------------------------------------------------------------
__global__ __launch_bounds__(256) void finalize(float* __restrict__ out,
                                                const float* __restrict__ b2)
{
    const int i = blockIdx.x * 256 + threadIdx.x;   // i = c*128 + b
    if (i >= BATCH * CLS) return;
    const int c = i >> 7;
    const int b = i & 127;
    float s = b2[0];
    #pragma unroll
    for (int k = 0; k < HSPLIT; k++) s += g_part[k][i];
    out[b * CLS + c] = 1.f / (1.f + expf(-s));
}

// ---------------------------------------------------------------------
extern "C" void kernel_launch(void* const* d_in, const int* in_sizes, int n_in,
                              void* d_out, int out_size)
{
    const float* img  = (const float*)d_in[0];
    const float* attr = (const float*)d_in[1];
    const float* W1   = (const float*)d_in[2];
    const float* b1   = (const float*)d_in[3];
    const float* W2   = (const float*)d_in[4];
    const float* b2   = (const float*)d_in[5];
    float* out = (float*)d_out;

    gemm_proj<<<dim3(HID / BN, 20, NSPLIT), 64>>>(img, attr, W1);
    reduce_parts<<<(HID * BATCH + CLS * HID + 255) / 256, 256>>>(b1);
    relscore<<<dim3((CLS + CT - 1) / CT, HSPLIT), 128>>>(W2);
    finalize<<<(BATCH * CLS + 255) / 256, 256>>>(out, b2);
}

// round 7
// speedup vs baseline: 1.3816x; 1.1947x over previous
#include <cuda_runtime.h>
#include <math.h>

#define BATCH 128
#define FEAT  1024
#define CLS   500
#define HID   512

#define HSPLIT 4
#define HCH    (HID / HSPLIT)    // 128

// Scratch (device globals: allocations forbidden)
__device__ float g_imgT[HID * BATCH];            // img @ W1a^T + b1, [h][b]
__device__ float g_attr[512 * HID];              // attr @ W1b^T, [c][h] (rows padded)
__device__ float g_part[HSPLIT][512 * BATCH];    // relscore partials [c*128+b]

// ---------- f32x2 helpers ----------
__device__ __forceinline__ unsigned long long pk2(float x, float y) {
    unsigned long long r;
    asm("mov.b64 %0, {%1, %2};" : "=l"(r) : "f"(x), "f"(y));
    return r;
}
__device__ __forceinline__ float2 unpk2(unsigned long long v) {
    float2 r;
    asm("mov.b64 {%0, %1}, %2;" : "=f"(r.x), "=f"(r.y) : "l"(v));
    return r;
}
__device__ __forceinline__ void ffma2(unsigned long long& d,
                                      unsigned long long a, unsigned long long b) {
    asm("fma.rn.f32x2 %0, %1, %2, %0;" : "+l"(d) : "l"(a), "l"(b));
}

// ---------------------------------------------------------------------
// Pipelined projection GEMM (no K-split).
// Virtual m: by 0..3 -> img rows (writes g_imgT [h][b] + b1)
//            by 4..19 -> attr rows (writes g_attr [c][h])
// BM=32 x BN=32 x BK=16, 128 threads, micro 2m x 4n (2 FFMA2-pairs),
// register-prefetch + double-buffered smem: one __syncthreads per k-iter.
// ---------------------------------------------------------------------
#define BM 32
#define BN 32
#define BK 16
#define KITERS (FEAT / BK)   // 64

__global__ __launch_bounds__(128) void gemm_proj(
    const float* __restrict__ img, const float* __restrict__ attr,
    const float* __restrict__ W1, const float* __restrict__ b1)
{
    __shared__ float As[2][BK][BM + 4];   // [buf][k][m], row 144B (16B-mult)
    __shared__ float Bs[2][BK][BN + 4];   // [buf][k][n]

    const int tid = threadIdx.x;
    const int tx  = tid & 7;              // 4 n each
    const int ty  = tid >> 3;             // 2 m each (0..15)
    const int by  = blockIdx.y;           // 0..19
    const int n0  = blockIdx.x * BN;

    const bool is_img = (by < 4);
    const float* A    = is_img ? img : attr;
    const int row0    = is_img ? by * BM : (by - 4) * BM;
    const int rowsM   = is_img ? BATCH : CLS;
    const int kWoff   = is_img ? 0 : FEAT;

    // loader lanes: each thread 1 float4 of A and 1 of B per iter
    const int lm = tid >> 2;              // 0..31 (row within tile)
    const int lk = (tid & 3) * 4;         // k-quad

    const float* Arow = (row0 + lm < rowsM) ? &A[(size_t)(row0 + lm) * FEAT + lk] : nullptr;
    const float* Brow = &W1[(size_t)(n0 + lm) * (2 * FEAT) + kWoff + lk];

    unsigned long long acc00 = 0ull, acc01 = 0ull, acc10 = 0ull, acc11 = 0ull;

    // prefetch iter 0
    float4 a_reg = Arow ? *(const float4*)Arow : make_float4(0.f, 0.f, 0.f, 0.f);
    float4 b_reg = *(const float4*)Brow;

    for (int it = 0; it < KITERS; it++) {
        const int p = it & 1;
        // stage current tile (transposed to [k][*])
        As[p][lk + 0][lm] = a_reg.x;
        As[p][lk + 1][lm] = a_reg.y;
        As[p][lk + 2][lm] = a_reg.z;
        As[p][lk + 3][lm] = a_reg.w;
        Bs[p][lk + 0][lm] = b_reg.x;
        Bs[p][lk + 1][lm] = b_reg.y;
        Bs[p][lk + 2][lm] = b_reg.z;
        Bs[p][lk + 3][lm] = b_reg.w;
        __syncthreads();

        // prefetch next tile (LDG latency hidden behind compute below)
        if (it + 1 < KITERS) {
            const int ko = (it + 1) * BK;
            a_reg = Arow ? *(const float4*)(Arow + ko) : make_float4(0.f, 0.f, 0.f, 0.f);
            b_reg = *(const float4*)(Brow + ko);
        }

        #pragma unroll
        for (int kk = 0; kk < BK; kk++) {
            float2 a2 = *(float2*)&As[p][kk][ty * 2];          // broadcast-friendly
            ulonglong2 bb = *(ulonglong2*)&Bs[p][kk][tx * 4];  // conflict-free
            unsigned long long a0 = pk2(a2.x, a2.x);
            unsigned long long a1 = pk2(a2.y, a2.y);
            ffma2(acc00, a0, bb.x); ffma2(acc01, a0, bb.y);
            ffma2(acc10, a1, bb.x); ffma2(acc11, a1, bb.y);
        }
        __syncthreads();
    }

    const int h = n0 + tx * 4;
    if (is_img) {
        const int b = row0 + ty * 2;
        float2 v00 = unpk2(acc00), v01 = unpk2(acc01);
        float2 v10 = unpk2(acc10), v11 = unpk2(acc11);
        const float bb0 = b1[h + 0], bb1 = b1[h + 1];
        const float bb2 = b1[h + 2], bb3 = b1[h + 3];
        g_imgT[(h + 0) * BATCH + b]     = v00.x + bb0;
        g_imgT[(h + 1) * BATCH + b]     = v00.y + bb1;
        g_imgT[(h + 2) * BATCH + b]     = v01.x + bb2;
        g_imgT[(h + 3) * BATCH + b]     = v01.y + bb3;
        g_imgT[(h + 0) * BATCH + b + 1] = v10.x + bb0;
        g_imgT[(h + 1) * BATCH + b + 1] = v10.y + bb1;
        g_imgT[(h + 2) * BATCH + b + 1] = v11.x + bb2;
        g_imgT[(h + 3) * BATCH + b + 1] = v11.y + bb3;
    } else {
        const int c = row0 + ty * 2;
        if (c < CLS) {
            ulonglong2 v; v.x = acc00; v.y = acc01;
            *(ulonglong2*)&g_attr[(size_t)c * HID + h] = v;
        }
        if (c + 1 < CLS) {
            ulonglong2 v; v.x = acc10; v.y = acc11;
            *(ulonglong2*)&g_attr[(size_t)(c + 1) * HID + h] = v;
        }
    }
}

// ---------------------------------------------------------------------
// part[hs][c,b] = sum_{h in 128-chunk} relu(imgT[h,b] + attr[c,h]) * W2[h]
// Grid: (63 c-tiles of 8, 4 h-splits). 128 threads = one per b.
// ---------------------------------------------------------------------
#define CT 8

__global__ __launch_bounds__(128) void relscore(const float* __restrict__ W2)
{
    __shared__ float attr8[HCH][CT];   // rows 32B: aligned broadcast float4 reads
    __shared__ float w2s[HCH];

    const int b  = threadIdx.x;
    const int c0 = blockIdx.x * CT;
    const int h0 = blockIdx.y * HCH;

    // fill: t -> (cc = t>>7, hh = t&127): coalesced global reads
    #pragma unroll
    for (int i = 0; i < CT; i++) {
        const int t  = i * 128 + b;
        const int cc = t >> 7, hh = t & 127;
        const int c  = c0 + cc;
        attr8[hh][cc] = (c < CLS) ? g_attr[(size_t)c * HID + h0 + hh] : 0.f;
    }
    w2s[b] = W2[h0 + b];
    __syncthreads();

    float acc[CT];
    #pragma unroll
    for (int i = 0; i < CT; i++) acc[i] = 0.f;

    const float* ip = g_imgT + (size_t)h0 * BATCH + b;

    #pragma unroll 8
    for (int hh = 0; hh < HCH; hh++) {
        const float iv = ip[(size_t)hh * BATCH];   // coalesced over threads
        const float w  = w2s[hh];
        float4 a0 = *(float4*)&attr8[hh][0];       // warp-broadcast
        float4 a1 = *(float4*)&attr8[hh][4];
        acc[0] += fmaxf(iv + a0.x, 0.f) * w;
        acc[1] += fmaxf(iv + a0.y, 0.f) * w;
        acc[2] += fmaxf(iv + a0.z, 0.f) * w;
        acc[3] += fmaxf(iv + a0.w, 0.f) * w;
        acc[4] += fmaxf(iv + a1.x, 0.f) * w;
        acc[5] += fmaxf(iv + a1.y, 0.f) * w;
        acc[6] += fmaxf(iv + a1.z, 0.f) * w;
        acc[7] += fmaxf(iv + a1.w, 0.f) * w;
    }

    float* part = g_part[blockIdx.y];
    #pragma unroll
    for (int cc = 0; cc < CT; cc++) {
        const int c = c0 + cc;
        if (c < CLS) part[c * BATCH + b] = acc[cc];   // coalesced over b
    }
}

// ---------------------------------------------------------------------
// out[b, c0..c0+3] = sigmoid(sum of 4 partials + b2), float4 store.
// Grid: 125 blocks x 128 threads (thread = b, block = 4 c's).
// ---------------------------------------------------------------------
__global__ __launch_bounds__(128) void finalize(float* __restrict__ out,
                                                const float* __restrict__ b2)
{
    const int b  = threadIdx.x;
    const int c0 = blockIdx.x * 4;
    const float bias = b2[0];

    float4 r;
    float* rv = (float*)&r;
    #pragma unroll
    for (int j = 0; j < 4; j++) {
        const int idx = (c0 + j) * BATCH + b;
        float s = bias;
        #pragma unroll
        for (int k = 0; k < HSPLIT; k++) s += g_part[k][idx];   // coalesced
        rv[j] = 1.f / (1.f + __expf(-s));
    }
    *(float4*)&out[(size_t)b * CLS + c0] = r;   // 16B-aligned (c0 % 4 == 0, CLS % 4 == 0)
}

// ---------------------------------------------------------------------
extern "C" void kernel_launch(void* const* d_in, const int* in_sizes, int n_in,
                              void* d_out, int out_size)
{
    const float* img  = (const float*)d_in[0];
    const float* attr = (const float*)d_in[1];
    const float* W1   = (const float*)d_in[2];
    const float* b1   = (const float*)d_in[3];
    const float* W2   = (const float*)d_in[4];
    const float* b2   = (const float*)d_in[5];
    float* out = (float*)d_out;

    gemm_proj<<<dim3(HID / BN, 20), 128>>>(img, attr, W1, b1);     // 320 blocks
    relscore<<<dim3((CLS + CT - 1) / CT, HSPLIT), 128>>>(W2);      // 252 blocks
    finalize<<<CLS / 4, 128>>>(out, b2);                           // 125 blocks
}